// round 14
// baseline (speedup 1.0000x reference)
#include <cuda_runtime.h>

// out = segment_sum(source[src_idx], seg_ids); softmax over singleton axis==1,
// so all attention machinery is dead code.
//
// SINGLE kernel, segment-ownership, zero atomics:
//  seg_ids sorted -> each segment is owned by the warp whose (balanced,
//  oct-granular) edge range contains the segment's first edge. A warp skips a
//  leading partial segment, processes its range with the proven R10 oct loop
//  (8 independent float2 gathers batched at iteration top, uniform-oct fast
//  path), extends past its range end until its last segment terminates, and
//  STG-stores every segment it closes. Empty-node rows are zero-stored by the
//  owner of the preceding segment (gap fill on each transition), warp 0 fills
//  [0, first_seg), the final owner fills (last_seg, N). Output written exactly
//  once per row -> no zero kernel, no atomicAdd, one launch.
//
// Inputs: 0 source[N,64] f32, 2 src_idx[E] i32, 3 seg_ids[E] i32 (sorted).

#define NBLOCKS 888
#define NTHREADS 256
#define NWARPS (NBLOCKS * (NTHREADS / 32))

__global__ void __launch_bounds__(NTHREADS)
seg_gather_sum_kernel(const float2* __restrict__ src2,
                      const int4* __restrict__ src_idx4,
                      const int4* __restrict__ seg_ids4,
                      float* __restrict__ out,
                      int E, int N) {
    const int* __restrict__ src_idx = (const int*)src_idx4;
    const int* __restrict__ seg_ids = (const int*)seg_ids4;

    const int lane = threadIdx.x & 31;
    const int warp = blockIdx.x * (NTHREADS / 32) + (threadIdx.x >> 5);

    // balanced partition of 8-edge groups ("octs") across all warps
    const int noct_total = (E + 7) >> 3;
    const int q = noct_total / NWARPS;
    const int r = noct_total - q * NWARPS;
    const int o0 = warp * q + (warp < r ? warp : r);
    const int mycnt = q + (warp < r ? 1 : 0);
    if (mycnt == 0) return;

    const int e0 = o0 << 3;
    int e1 = e0 + (mycnt << 3);
    if (e1 > E) e1 = E;

    // head gap: rows before the very first segment
    if (e0 == 0) {
        int s_first = __ldg(&seg_ids[0]);
        for (int z = 0; z < s_first; ++z)
            ((float2*)&out[(long long)z * 64])[lane] = make_float2(0.f, 0.f);
    }

    // A) skip leading partial segment (owned by an upstream warp)
    int a = e0;
    if (e0 > 0) {
        int s0 = __ldg(&seg_ids[e0]);
        if (__ldg(&seg_ids[e0 - 1]) == s0) {
            for (;;) {
                int idx = a + lane;
                bool diff = (idx >= E) || (__ldg(&seg_ids[idx]) != s0);
                unsigned m = __ballot_sync(0xffffffffu, diff);
                if (m) { a += __ffs(m) - 1; break; }
                a += 32;
            }
            if (a >= e1) return;  // whole range swallowed; owner handles all
        }
    }

    int cur = __ldg(&seg_ids[a]);
    float ax = 0.f, ay = 0.f;
    int e = a;

    // store closed segment `cur`, zero-fill gap rows, switch to NS
#define FLUSH_TO(NS)                                                        \
    do {                                                                    \
        ((float2*)&out[(long long)cur * 64])[lane] = make_float2(ax, ay);   \
        for (int z = cur + 1; z < (NS); ++z)                                \
            ((float2*)&out[(long long)z * 64])[lane] =                      \
                make_float2(0.f, 0.f);                                      \
        ax = 0.f; ay = 0.f; cur = (NS);                                     \
    } while (0)

#define ACC(S, V)                                                           \
    do {                                                                    \
        if ((S) != cur) FLUSH_TO(S);                                        \
        ax += (V).x; ay += (V).y;                                           \
    } while (0)

    // B1) scalar head up to 8-alignment
    int head_end = (a + 7) & ~7;
    if (head_end > e1) head_end = e1;
    for (; e < head_end; ++e) {
        int s = __ldg(&seg_ids[e]);
        int idx = __ldg(&src_idx[e]);
        float2 v = __ldg(&src2[(long long)idx * 32 + lane]);
        ACC(s, v);
    }

    // B2) main oct loop (identical hot path to R10)
    for (; e + 8 <= e1; e += 8) {
        int4 sa = __ldg(&seg_ids4[(e >> 2) + 0]);
        int4 sb = __ldg(&seg_ids4[(e >> 2) + 1]);
        int4 ia = __ldg(&src_idx4[(e >> 2) + 0]);
        int4 ib = __ldg(&src_idx4[(e >> 2) + 1]);

        float2 v0 = __ldg(&src2[(long long)ia.x * 32 + lane]);
        float2 v1 = __ldg(&src2[(long long)ia.y * 32 + lane]);
        float2 v2 = __ldg(&src2[(long long)ia.z * 32 + lane]);
        float2 v3 = __ldg(&src2[(long long)ia.w * 32 + lane]);
        float2 v4 = __ldg(&src2[(long long)ib.x * 32 + lane]);
        float2 v5 = __ldg(&src2[(long long)ib.y * 32 + lane]);
        float2 v6 = __ldg(&src2[(long long)ib.z * 32 + lane]);
        float2 v7 = __ldg(&src2[(long long)ib.w * 32 + lane]);

        if (sa.x == sb.w) {
            if (sa.x != cur) FLUSH_TO(sa.x);
            ax += ((v0.x + v1.x) + (v2.x + v3.x)) + ((v4.x + v5.x) + (v6.x + v7.x));
            ay += ((v0.y + v1.y) + (v2.y + v3.y)) + ((v4.y + v5.y) + (v6.y + v7.y));
        } else {
            ACC(sa.x, v0);
            ACC(sa.y, v1);
            ACC(sa.z, v2);
            ACC(sa.w, v3);
            ACC(sb.x, v4);
            ACC(sb.y, v5);
            ACC(sb.z, v6);
            ACC(sb.w, v7);
        }
    }

    // B3) scalar tail to e1 (last warp when E % 8 != 0)
    for (; e < e1; ++e) {
        int s = __ldg(&seg_ids[e]);
        int idx = __ldg(&src_idx[e]);
        float2 v = __ldg(&src2[(long long)idx * 32 + lane]);
        ACC(s, v);
    }
#undef ACC
#undef FLUSH_TO

    // C) extend: running segment may continue past e1 — we own it to its end
    while (e < E) {
        int idx = e + lane;
        bool cont = (idx < E) && (__ldg(&seg_ids[idx]) == cur);
        unsigned m = __ballot_sync(0xffffffffu, cont);
        if ((m & 1u) == 0u) break;
        int n = (~m == 0u) ? 32 : (__ffs(~m) - 1);
        int gidx = 0;
        if (idx < E) gidx = __ldg(&src_idx[idx]);
        for (int k = 0; k < n; ++k) {
            int g = __shfl_sync(0xffffffffu, gidx, k);
            float2 v = __ldg(&src2[(long long)g * 32 + lane]);
            ax += v.x; ay += v.y;
        }
        e += n;
        if (n < 32) break;
    }

    // D) final store + trailing gap fill up to the next owned segment (or N)
    ((float2*)&out[(long long)cur * 64])[lane] = make_float2(ax, ay);
    int s_next = (e < E) ? __ldg(&seg_ids[e]) : N;
    for (int z = cur + 1; z < s_next; ++z)
        ((float2*)&out[(long long)z * 64])[lane] = make_float2(0.f, 0.f);
}

extern "C" void kernel_launch(void* const* d_in, const int* in_sizes, int n_in,
                              void* d_out, int out_size) {
    const float* source  = (const float*)d_in[0];
    const int*   src_idx = (const int*)d_in[2];
    const int*   seg_ids = (const int*)d_in[3];
    float* out = (float*)d_out;

    int E = in_sizes[2];
    int N = out_size / 64;

    seg_gather_sum_kernel<<<NBLOCKS, NTHREADS>>>(
        (const float2*)source, (const int4*)src_idx, (const int4*)seg_ids,
        out, E, N);
}

// round 15
// speedup vs baseline: 1.1481x; 1.1481x over previous
#include <cuda_runtime.h>
#include <cuda_fp16.h>

// out = segment_sum(source[src_idx], seg_ids); softmax over singleton axis==1,
// so all attention machinery is dead code.
//
// R13 fp16 skeleton with the residency fix: the fp16 gather kernel compiles to
// 32 regs -> 8 blocks/SM fit, so launch 1184 = 148*8 blocks (single balanced
// wave, 64 warps/SM, 512 outstanding gathers/SM vs 384 before). Lane holds one
// half2 (2 cols): warp gather = 128B row = 1 L1 wavefront / 1 L2 line per
// edge. 8 independent gathers per oct, loads batched at iteration top
// (manual pipelining regressed twice). Uniform-oct fast path. Sorted seg_ids:
// interior flush = STG, boundary flush = atomicAdd. f32 accumulation
// (rel_err ~2e-4 vs 1e-3 budget).
//
// Inputs: 0 source[N,64] f32, 2 src_idx[E] i32, 3 seg_ids[E] i32 (sorted).

#define N_NODES_MAX 100000
#define NBLOCKS 1184
#define NTHREADS 256
#define NWARPS (NBLOCKS * (NTHREADS / 32))

__device__ __half2 g_src_h2[N_NODES_MAX * 32];   // 12.8 MB fp16 source

__global__ void __launch_bounds__(256)
prep_kernel(const float2* __restrict__ src2, int n_h2,
            float4* __restrict__ out4, int n4) {
    int i = blockIdx.x * blockDim.x + threadIdx.x;
    int stride = gridDim.x * blockDim.x;
    for (int j = i; j < n_h2; j += stride)
        g_src_h2[j] = __float22half2_rn(src2[j]);
    for (int j = i; j < n4; j += stride)
        out4[j] = make_float4(0.f, 0.f, 0.f, 0.f);
}

__global__ void __launch_bounds__(NTHREADS)
seg_gather_sum_kernel(const int4* __restrict__ src_idx4,
                      const int4* __restrict__ seg_ids4,
                      float* __restrict__ out,
                      int E) {
    const __half2* __restrict__ srcH = g_src_h2;
    const int* __restrict__ src_idx = (const int*)src_idx4;
    const int* __restrict__ seg_ids = (const int*)seg_ids4;

    const int lane = threadIdx.x & 31;
    const int warp = blockIdx.x * (NTHREADS / 32) + (threadIdx.x >> 5);

    // balanced partition of 8-edge groups ("octs") across all warps
    const int noct_total = (E + 7) >> 3;
    const int q = noct_total / NWARPS;
    const int r = noct_total - q * NWARPS;
    const int o0 = warp * q + (warp < r ? warp : r);
    const int mycnt = q + (warp < r ? 1 : 0);
    if (mycnt == 0) return;

    int e = o0 << 3;
    int e1 = e + (mycnt << 3);
    if (e1 > E) e1 = E;

    const int first_seg = seg_ids[e];
    int cur = first_seg;
    float ax = 0.f, ay = 0.f;

#define FLUSH()                                                         \
    do {                                                                \
        float2* p = (float2*)&out[(long long)cur * 64 + 2 * lane];      \
        if (cur == first_seg) {                                         \
            atomicAdd(&((float*)p)[0], ax);                             \
            atomicAdd(&((float*)p)[1], ay);                             \
        } else {                                                        \
            *p = make_float2(ax, ay);                                   \
        }                                                               \
        ax = 0.f; ay = 0.f;                                             \
    } while (0)

#define ACC(S, H)                                                       \
    do {                                                                \
        if ((S) != cur) { FLUSH(); cur = (S); }                         \
        float2 _f = __half22float2(H);                                  \
        ax += _f.x; ay += _f.y;                                         \
    } while (0)

    int noct = (e1 - e) >> 3;
    for (int t = 0; t < noct; ++t, e += 8) {
        int4 sa = __ldg(&seg_ids4[(e >> 2) + 0]);
        int4 sb = __ldg(&seg_ids4[(e >> 2) + 1]);
        int4 ia = __ldg(&src_idx4[(e >> 2) + 0]);
        int4 ib = __ldg(&src_idx4[(e >> 2) + 1]);

        __half2 v0 = __ldg(&srcH[(long long)ia.x * 32 + lane]);
        __half2 v1 = __ldg(&srcH[(long long)ia.y * 32 + lane]);
        __half2 v2 = __ldg(&srcH[(long long)ia.z * 32 + lane]);
        __half2 v3 = __ldg(&srcH[(long long)ia.w * 32 + lane]);
        __half2 v4 = __ldg(&srcH[(long long)ib.x * 32 + lane]);
        __half2 v5 = __ldg(&srcH[(long long)ib.y * 32 + lane]);
        __half2 v6 = __ldg(&srcH[(long long)ib.z * 32 + lane]);
        __half2 v7 = __ldg(&srcH[(long long)ib.w * 32 + lane]);

        if (sa.x == sb.w) {
            // whole oct in one segment: pairwise f32 tree, one compare
            if (sa.x != cur) { FLUSH(); cur = sa.x; }
            float2 f0 = __half22float2(v0);
            float2 f1 = __half22float2(v1);
            float2 f2 = __half22float2(v2);
            float2 f3 = __half22float2(v3);
            float2 f4 = __half22float2(v4);
            float2 f5 = __half22float2(v5);
            float2 f6 = __half22float2(v6);
            float2 f7 = __half22float2(v7);
            ax += ((f0.x + f1.x) + (f2.x + f3.x)) + ((f4.x + f5.x) + (f6.x + f7.x));
            ay += ((f0.y + f1.y) + (f2.y + f3.y)) + ((f4.y + f5.y) + (f6.y + f7.y));
        } else {
            ACC(sa.x, v0);
            ACC(sa.y, v1);
            ACC(sa.z, v2);
            ACC(sa.w, v3);
            ACC(sb.x, v4);
            ACC(sb.y, v5);
            ACC(sb.z, v6);
            ACC(sb.w, v7);
        }
    }

    // tail (E % 8 != 0 only in the last warp's range)
    for (; e < e1; ++e) {
        int s = __ldg(&seg_ids[e]);
        int idx = __ldg(&src_idx[e]);
        __half2 v = __ldg(&srcH[(long long)idx * 32 + lane]);
        ACC(s, v);
    }
#undef ACC
#undef FLUSH

    // running segment may continue into the next warp's range -> atomic
    atomicAdd(&out[(long long)cur * 64 + 2 * lane + 0], ax);
    atomicAdd(&out[(long long)cur * 64 + 2 * lane + 1], ay);
}

extern "C" void kernel_launch(void* const* d_in, const int* in_sizes, int n_in,
                              void* d_out, int out_size) {
    const float* source  = (const float*)d_in[0];
    const int*   src_idx = (const int*)d_in[2];
    const int*   seg_ids = (const int*)d_in[3];
    float* out = (float*)d_out;

    int E = in_sizes[2];
    int n_h2 = in_sizes[0] / 2;
    int n4 = out_size / 4;

    // 1) fp16 convert + zero the output (single streaming pass)
    prep_kernel<<<NBLOCKS, NTHREADS>>>((const float2*)source, n_h2,
                                       (float4*)d_out, n4);

    // 2) gather + segment-sum, single balanced wave at 8 blocks/SM
    seg_gather_sum_kernel<<<NBLOCKS, NTHREADS>>>(
        (const int4*)src_idx, (const int4*)seg_ids, out, E);
}

// round 16
// speedup vs baseline: 1.3478x; 1.1739x over previous
#include <cuda_runtime.h>

// out = segment_sum(source[src_idx], seg_ids); softmax over singleton axis==1,
// so all attention machinery is dead code.
//
// R10 f32 skeleton (proven fastest gather: 33.9us) + targeted zero-init:
//  * Only rows that receive atomicAdd need zeroing: each warp's first_seg
//    (seg_ids[e0(w)]) and final running segment (seg_ids[e1(w)-1]). Interior
//    segments are flushed with full STG (overwrites harness poison). The warp
//    partition is closed-form, so a pre-kernel zeroes exactly those ~14K rows
//    (one warp per boundary row) instead of streaming all 25.6MB.
//  * Gathers use __ldcg (L2-only): ~1% L1 hit rate on the random row stream,
//    so skip L1 fills (L1 was the top pipe at 67%).
// Hot loop unchanged: lane holds 2 cols (float2), 8 independent gathers per
// 8-edge oct batched at iteration top, uniform-oct fast path, balanced oct
// partition over a single 888-block wave.
//
// Inputs: 0 source[N,64] f32, 2 src_idx[E] i32, 3 seg_ids[E] i32 (sorted).

#define NBLOCKS 888
#define NTHREADS 256
#define NWARPS (NBLOCKS * (NTHREADS / 32))

// warp w's edge range [e0, e1) under the balanced oct partition
__device__ __forceinline__ void warp_range(int w, int E, int* pe0, int* pe1) {
    const int noct_total = (E + 7) >> 3;
    const int q = noct_total / NWARPS;
    const int r = noct_total - q * NWARPS;
    const int o0 = w * q + (w < r ? w : r);
    const int cnt = q + (w < r ? 1 : 0);
    int e0 = o0 << 3;
    int e1 = e0 + (cnt << 3);
    if (e1 > E) e1 = E;
    *pe0 = e0;
    *pe1 = (cnt == 0) ? e0 : e1;
}

// zero exactly the rows that will receive atomicAdd from the gather kernel
__global__ void __launch_bounds__(NTHREADS)
zero_boundary_kernel(const int* __restrict__ seg_ids,
                     float* __restrict__ out, int E) {
    const int t = blockIdx.x * (NTHREADS / 32) + (threadIdx.x >> 5); // warp id
    const int lane = threadIdx.x & 31;
    const int w = t >> 1;
    if (w >= NWARPS) return;
    int e0, e1;
    warp_range(w, E, &e0, &e1);
    if (e1 <= e0) return;
    int e = (t & 1) ? (e1 - 1) : e0;
    int row = __ldg(&seg_ids[e]);
    ((float2*)&out[(long long)row * 64])[lane] = make_float2(0.f, 0.f);
}

__global__ void __launch_bounds__(NTHREADS)
seg_gather_sum_kernel(const float2* __restrict__ src2,
                      const int4* __restrict__ src_idx4,
                      const int4* __restrict__ seg_ids4,
                      float* __restrict__ out,
                      int E) {
    const int* __restrict__ src_idx = (const int*)src_idx4;
    const int* __restrict__ seg_ids = (const int*)seg_ids4;

    const int lane = threadIdx.x & 31;
    const int warp = blockIdx.x * (NTHREADS / 32) + (threadIdx.x >> 5);

    int e, e1;
    warp_range(warp, E, &e, &e1);
    if (e1 <= e) return;

    const int first_seg = seg_ids[e];
    int cur = first_seg;
    float ax = 0.f, ay = 0.f;

#define FLUSH()                                                         \
    do {                                                                \
        float2* p = (float2*)&out[(long long)cur * 64 + 2 * lane];      \
        if (cur == first_seg) {                                         \
            atomicAdd(&((float*)p)[0], ax);                             \
            atomicAdd(&((float*)p)[1], ay);                             \
        } else {                                                        \
            *p = make_float2(ax, ay);                                   \
        }                                                               \
        ax = 0.f; ay = 0.f;                                             \
    } while (0)

#define ACC(S, V)                                                       \
    do {                                                                \
        if ((S) != cur) { FLUSH(); cur = (S); }                         \
        ax += (V).x; ay += (V).y;                                       \
    } while (0)

    int noct = (e1 - e) >> 3;
    for (int t = 0; t < noct; ++t, e += 8) {
        int4 sa = __ldg(&seg_ids4[(e >> 2) + 0]);
        int4 sb = __ldg(&seg_ids4[(e >> 2) + 1]);
        int4 ia = __ldg(&src_idx4[(e >> 2) + 0]);
        int4 ib = __ldg(&src_idx4[(e >> 2) + 1]);

        float2 v0 = __ldcg(&src2[(long long)ia.x * 32 + lane]);
        float2 v1 = __ldcg(&src2[(long long)ia.y * 32 + lane]);
        float2 v2 = __ldcg(&src2[(long long)ia.z * 32 + lane]);
        float2 v3 = __ldcg(&src2[(long long)ia.w * 32 + lane]);
        float2 v4 = __ldcg(&src2[(long long)ib.x * 32 + lane]);
        float2 v5 = __ldcg(&src2[(long long)ib.y * 32 + lane]);
        float2 v6 = __ldcg(&src2[(long long)ib.z * 32 + lane]);
        float2 v7 = __ldcg(&src2[(long long)ib.w * 32 + lane]);

        if (sa.x == sb.w) {
            // whole oct in one segment (common at mean degree 16)
            if (sa.x != cur) { FLUSH(); cur = sa.x; }
            ax += ((v0.x + v1.x) + (v2.x + v3.x)) + ((v4.x + v5.x) + (v6.x + v7.x));
            ay += ((v0.y + v1.y) + (v2.y + v3.y)) + ((v4.y + v5.y) + (v6.y + v7.y));
        } else {
            ACC(sa.x, v0);
            ACC(sa.y, v1);
            ACC(sa.z, v2);
            ACC(sa.w, v3);
            ACC(sb.x, v4);
            ACC(sb.y, v5);
            ACC(sb.z, v6);
            ACC(sb.w, v7);
        }
    }

    // tail (E % 8 != 0 only in the last warp's range)
    for (; e < e1; ++e) {
        int s = __ldg(&seg_ids[e]);
        int idx = __ldg(&src_idx[e]);
        float2 v = __ldcg(&src2[(long long)idx * 32 + lane]);
        ACC(s, v);
    }
#undef ACC
#undef FLUSH

    // running segment may continue into the next warp's range -> atomic
    atomicAdd(&out[(long long)cur * 64 + 2 * lane + 0], ax);
    atomicAdd(&out[(long long)cur * 64 + 2 * lane + 1], ay);
}

extern "C" void kernel_launch(void* const* d_in, const int* in_sizes, int n_in,
                              void* d_out, int out_size) {
    const float* source  = (const float*)d_in[0];
    const int*   src_idx = (const int*)d_in[2];
    const int*   seg_ids = (const int*)d_in[3];
    float* out = (float*)d_out;

    int E = in_sizes[2];

    // 1) zero exactly the atomic-target rows (2 per gather warp)
    int nzwarps = NWARPS * 2;
    int nzblocks = (nzwarps + (NTHREADS / 32) - 1) / (NTHREADS / 32);
    zero_boundary_kernel<<<nzblocks, NTHREADS>>>(seg_ids, out, E);

    // 2) gather + segment-sum, single balanced wave
    seg_gather_sum_kernel<<<NBLOCKS, NTHREADS>>>(
        (const float2*)source, (const int4*)src_idx, (const int4*)seg_ids,
        out, E);
}